// round 11
// baseline (speedup 1.0000x reference)
#include <cuda_runtime.h>
#include <math.h>

#define T_STEPS 4096
#define BATCH   32
#define DIN     256
#define HID     256
#define GATES   1024
#define OUTD    512
#define CL_SZ   8
#define NBLK    128

__device__ float g_xz_f[(size_t)T_STEPS * BATCH * GATES];
__device__ float g_xz_b[(size_t)T_STEPS * BATCH * GATES];
__device__ float g_houts[(size_t)T_STEPS * BATCH * 2 * HID];

__device__ __forceinline__ float sigf(float x)  { return 1.0f / (1.0f + __expf(-x)); }

__device__ __forceinline__ unsigned long long ffma2(
    unsigned long long a, unsigned long long b, unsigned long long c) {
    unsigned long long d;
    asm("fma.rn.f32x2 %0, %1, %2, %3;" : "=l"(d) : "l"(a), "l"(b), "l"(c));
    return d;
}
__device__ __forceinline__ unsigned long long bcast2(float a) {
    unsigned long long d;
    asm("mov.b64 %0, {%1, %1};" : "=l"(d) : "f"(a));
    return d;
}
__device__ __forceinline__ unsigned smem_u32(const void* p) {
    return (unsigned)__cvta_generic_to_shared(p);
}
__device__ __forceinline__ void mbar_wait_cl(unsigned addr, unsigned parity) {
    asm volatile(
        "{\n\t.reg .pred P;\n"
        "LW%=:\n\t"
        "mbarrier.try_wait.parity.acquire.cluster.shared::cta.b64 P, [%0], %1, 0x989680;\n\t"
        "@P bra LD%=;\n\t"
        "bra LW%=;\n"
        "LD%=:\n\t}"
        :: "r"(addr), "r"(parity) : "memory");
}

#define CLUSTER_SYNC() do { \
    asm volatile("barrier.cluster.arrive.aligned;" ::: "memory"); \
    asm volatile("barrier.cluster.wait.aligned;"   ::: "memory"); \
} while (0)

// ---------------- GEMM 1: xz = x @ Wx + bias (unchanged, passing) -----------
__global__ void __launch_bounds__(256) k_gemm_xz(
    const float* __restrict__ A, const float* __restrict__ W,
    const float* __restrict__ bias, float* __restrict__ C)
{
    __shared__ float As[8][128];
    __shared__ float Bs[8][128];
    const int tid = threadIdx.x;
    const int n0 = blockIdx.x << 7, m0 = blockIdx.y << 7;
    const int am = tid >> 1, ak = (tid & 1) << 2;
    const int bk = tid >> 5, bn = (tid & 31) << 2;
    const int ty = tid >> 4, tx = tid & 15;
    unsigned long long acc2[8][4] = {};

    for (int k0 = 0; k0 < DIN; k0 += 8) {
        float4 av = *(const float4*)(A + (size_t)(m0 + am) * DIN + k0 + ak);
        float4 bv = *(const float4*)(W + (size_t)(k0 + bk) * GATES + n0 + bn);
        __syncthreads();
        As[ak + 0][am] = av.x; As[ak + 1][am] = av.y;
        As[ak + 2][am] = av.z; As[ak + 3][am] = av.w;
        *(float4*)&Bs[bk][bn] = bv;
        __syncthreads();
#pragma unroll
        for (int kk = 0; kk < 8; kk++) {
            float ar[8];
            *(float4*)&ar[0] = *(const float4*)&As[kk][(ty << 3) + 0];
            *(float4*)&ar[4] = *(const float4*)&As[kk][(ty << 3) + 4];
            union { float4 f; unsigned long long u[2]; } B0, B1;
            B0.f = *(const float4*)&Bs[kk][(tx << 3) + 0];
            B1.f = *(const float4*)&Bs[kk][(tx << 3) + 4];
#pragma unroll
            for (int r = 0; r < 8; r++) {
                unsigned long long a2 = bcast2(ar[r]);
                acc2[r][0] = ffma2(a2, B0.u[0], acc2[r][0]);
                acc2[r][1] = ffma2(a2, B0.u[1], acc2[r][1]);
                acc2[r][2] = ffma2(a2, B1.u[0], acc2[r][2]);
                acc2[r][3] = ffma2(a2, B1.u[1], acc2[r][3]);
            }
        }
    }
    float bi[8];
    *(float4*)&bi[0] = *(const float4*)(bias + n0 + (tx << 3) + 0);
    *(float4*)&bi[4] = *(const float4*)(bias + n0 + (tx << 3) + 4);
#pragma unroll
    for (int r = 0; r < 8; r++) {
        int m = m0 + (ty << 3) + r;
        int t = m & (T_STEPS - 1), b = m >> 12;
        float* dst = C + (size_t)(t * BATCH + b) * GATES + n0 + (tx << 3);
        union { unsigned long long u; float f[2]; } U;
        float o[8];
#pragma unroll
        for (int c4 = 0; c4 < 4; c4++) {
            U.u = acc2[r][c4];
            o[2 * c4 + 0] = U.f[0] + bi[2 * c4 + 0];
            o[2 * c4 + 1] = U.f[1] + bi[2 * c4 + 1];
        }
        *(float4*)(dst + 0) = *(float4*)&o[0];
        *(float4*)(dst + 4) = *(float4*)&o[4];
    }
}

// ---------------- GEMM 2: out = relu(h_cat) @ W_dense + b (unchanged) ------
__global__ void __launch_bounds__(256) k_gemm_dense(
    const float* __restrict__ W, const float* __restrict__ bias,
    float* __restrict__ out)
{
    __shared__ float As[8][128];
    __shared__ float Bs[8][128];
    const int tid = threadIdx.x;
    const int n0 = blockIdx.x << 7, m0 = blockIdx.y << 7;
    const int am = tid >> 1, ak = (tid & 1) << 2;
    const int bk = tid >> 5, bn = (tid & 31) << 2;
    const int ty = tid >> 4, tx = tid & 15;
    unsigned long long acc2[8][4] = {};

    for (int k0 = 0; k0 < 2 * HID; k0 += 8) {
        float4 av = *(const float4*)(g_houts + (size_t)(m0 + am) * (2 * HID) + k0 + ak);
        av.x = fmaxf(av.x, 0.f); av.y = fmaxf(av.y, 0.f);
        av.z = fmaxf(av.z, 0.f); av.w = fmaxf(av.w, 0.f);
        float4 bv = *(const float4*)(W + (size_t)(k0 + bk) * OUTD + n0 + bn);
        __syncthreads();
        As[ak + 0][am] = av.x; As[ak + 1][am] = av.y;
        As[ak + 2][am] = av.z; As[ak + 3][am] = av.w;
        *(float4*)&Bs[bk][bn] = bv;
        __syncthreads();
#pragma unroll
        for (int kk = 0; kk < 8; kk++) {
            float ar[8];
            *(float4*)&ar[0] = *(const float4*)&As[kk][(ty << 3) + 0];
            *(float4*)&ar[4] = *(const float4*)&As[kk][(ty << 3) + 4];
            union { float4 f; unsigned long long u[2]; } B0, B1;
            B0.f = *(const float4*)&Bs[kk][(tx << 3) + 0];
            B1.f = *(const float4*)&Bs[kk][(tx << 3) + 4];
#pragma unroll
            for (int r = 0; r < 8; r++) {
                unsigned long long a2 = bcast2(ar[r]);
                acc2[r][0] = ffma2(a2, B0.u[0], acc2[r][0]);
                acc2[r][1] = ffma2(a2, B0.u[1], acc2[r][1]);
                acc2[r][2] = ffma2(a2, B1.u[0], acc2[r][2]);
                acc2[r][3] = ffma2(a2, B1.u[1], acc2[r][3]);
            }
        }
    }
    float bi[8];
    *(float4*)&bi[0] = *(const float4*)(bias + n0 + (tx << 3) + 0);
    *(float4*)&bi[4] = *(const float4*)(bias + n0 + (tx << 3) + 4);
#pragma unroll
    for (int r = 0; r < 8; r++) {
        int m = m0 + (ty << 3) + r;
        int b = m & 31, t = m >> 5;
        float* dst = out + ((size_t)b * T_STEPS + t) * OUTD + n0 + (tx << 3);
        union { unsigned long long u; float f[2]; } U;
        float o[8];
#pragma unroll
        for (int c4 = 0; c4 < 4; c4++) {
            U.u = acc2[r][c4];
            o[2 * c4 + 0] = U.f[0] + bi[2 * c4 + 0];
            o[2 * c4 + 1] = U.f[1] + bi[2 * c4 + 1];
        }
        *(float4*)(dst + 0) = *(float4*)&o[0];
        *(float4*)(dst + 4) = *(float4*)&o[4];
    }
}

// ---------------- Recurrence: batch-staggered, barrier-free ----------------
// 16 clusters x 8 CTAs x 512 thr. CTA owns 32 h-cols. Thread (w,l):
//   j = (w<<1)|(l>>4) local h-col, g=(l>>2)&3 gate, q=l&3 k-quarter.
// Per step, two phases (batch 0 then batch 1), each: per-warp mbar wait ->
// 16 LDS.128 + 32 FFMA2 -> 2 shfl.bfly (k reduce) + xz -> act (single exp)
// -> lead lanes (l%16==0): 3 shfl gate-gather, c/h update, 8 st.async
// (data+tx-signal) -> next phase. NO __syncthreads in the loop; batch B's
// compute hides batch A's DSMEM delivery.
__global__ void __cluster_dims__(CL_SZ, 1, 1) __launch_bounds__(512, 1) k_recur(
    const float* __restrict__ carry_c, const float* __restrict__ carry_h,
    const float* __restrict__ Wh_f, const float* __restrict__ Wh_b)
{
    // padded h: 4 slices of 68 floats (bank offset 4 per slice, conflict-free)
    __shared__ float h_s[2][2][272];           // [buf][batch][phys]
    __shared__ unsigned long long mb[4];       // [batch*2 + idx]

    const int tid  = threadIdx.x;
    const int w    = tid >> 5, l = tid & 31;
    const int rank = blockIdx.x & (CL_SZ - 1);
    const int b0   = (blockIdx.x >> 3) << 1;
    const int jl   = (w << 1) | (l >> 4);      // 0..31
    const int g    = (l >> 2) & 3;
    const int q    = l & 3;
    const int jglob = (rank << 5) + jl;        // 0..255
    const int gc    = (g << 8) + jglob;        // gate col in [0,1024)
    const bool lead = ((l & 15) == 0);         // lanes 0,16
    const int  physj = ((jglob >> 6) * 68) + (jglob & 63);

    // init h buffer 0 (both batches), logical k -> padded phys
    {
        const int X = tid >> 8, k = tid & 255;
        h_s[0][X][((k >> 6) * 68) + (k & 63)] =
            carry_h[(size_t)(b0 + X) * HID + k];
    }
    if (tid == 0) {
#pragma unroll
        for (int i = 0; i < 4; i++)
            asm volatile("mbarrier.init.shared.b64 [%0], %1;"
                         :: "r"(smem_u32(&mb[i])), "r"(1) : "memory");
    }

    float c2[2] = {0.f, 0.f};
    unsigned rem_h0[CL_SZ];    // peer addr of h_s[0][0][physj]
    unsigned rem_mb0[CL_SZ];   // peer addr of mb[0]
    if (lead) {
        c2[0] = carry_c[(size_t)(b0 + 0) * HID + jglob];
        c2[1] = carry_c[(size_t)(b0 + 1) * HID + jglob];
        unsigned lh = smem_u32(&h_s[0][0][physj]);
        unsigned lm = smem_u32(&mb[0]);
#pragma unroll
        for (int p = 0; p < CL_SZ; p++) {
            asm("mapa.shared::cluster.u32 %0, %1, %2;"
                : "=r"(rem_h0[p]) : "r"(lh), "r"(p));
            asm("mapa.shared::cluster.u32 %0, %1, %2;"
                : "=r"(rem_mb0[p]) : "r"(lm), "r"(p));
        }
    }
    __syncthreads();
    CLUSTER_SYNC();            // h bufs + mbars visible cluster-wide

    const unsigned TXB = CL_SZ * 32u * 4u;     // 1024 B per batch exchange
    const unsigned mb0a = smem_u32(&mb[0]);

    int gs = 0;
    for (int dir = 0; dir < 2; dir++) {
        const float* __restrict__ Wh = dir ? Wh_b : Wh_f;
        const float* __restrict__ xz = dir ? g_xz_b : g_xz_f;
        const int half = dir ? HID : 0;

        // register-resident weights: 64 k (quarter q) x 1 gate-col
        unsigned long long w2[32];
#pragma unroll
        for (int kk = 0; kk < 32; kk++) {
            union { float f[2]; unsigned long long u; } P;
            P.f[0] = Wh[(size_t)((q << 6) + 2 * kk + 0) * GATES + gc];
            P.f[1] = Wh[(size_t)((q << 6) + 2 * kk + 1) * GATES + gc];
            w2[kk] = P.u;
        }

        // prefetch xz for first step (all lanes; 4-lane broadcast per addr)
        float xzv[2];
        {
            const int t0 = dir ? (T_STEPS - 1) : 0;
            xzv[0] = __ldcg(xz + ((size_t)t0 * BATCH + b0 + 0) * GATES + gc);
            xzv[1] = __ldcg(xz + ((size_t)t0 * BATCH + b0 + 1) * GATES + gc);
        }

        for (int s = 0; s < T_STEPS; s++, gs++) {
            const int t   = dir ? (T_STEPS - 1 - s) : s;
            const int cur = gs & 1, nxt = cur ^ 1;
            const int tn  = dir ? (T_STEPS - 2 - s) : (s + 1);

#pragma unroll
            for (int X = 0; X < 2; X++) {
                // wait exchange gs-1 for batch X (per-warp; no CTA barrier)
                if (gs > 0) {
                    const int e = gs - 1;
                    mbar_wait_cl(mb0a + (unsigned)(((X << 1) | (e & 1)) << 3),
                                 (unsigned)((e >> 1) & 1));
                }
                if (tid == 0)   // declare exchange gs bytes for batch X
                    asm volatile(
                        "mbarrier.arrive.expect_tx.shared.b64 _, [%0], %1;"
                        :: "r"(mb0a + (unsigned)(((X << 1) | (gs & 1)) << 3)),
                           "r"(TXB) : "memory");

                // consume prefetched xz, immediately prefetch next step's
                const float xzu = xzv[X];
                if (s + 1 < T_STEPS)
                    xzv[X] = __ldcg(xz + ((size_t)tn * BATCH + b0 + X) * GATES + gc);

                // dot product over this thread's 64-k quarter
                unsigned long long a = 0ull;
                {
                    const float4* hp = (const float4*)&h_s[cur][X][q * 68];
#pragma unroll
                    for (int i = 0; i < 16; i++) {
                        union { float4 f; unsigned long long u[2]; } U;
                        U.f = hp[i];
                        a = ffma2(U.u[0], w2[2 * i + 0], a);
                        a = ffma2(U.u[1], w2[2 * i + 1], a);
                    }
                }
                union { unsigned long long u; float f[2]; } A; A.u = a;
                float z = A.f[0] + A.f[1];
                z += __shfl_xor_sync(0xffffffffu, z, 1);
                z += __shfl_xor_sync(0xffffffffu, z, 2);
                z += xzu;

                // activation: tanh(z) = 2*sig(2z)-1 (one exp chain, no branch)
                const float zin = (g == 2) ? (z + z) : z;
                const float sg  = sigf(zin);
                const float act = (g == 2) ? (2.f * sg - 1.f) : sg;

                // gate gather (sources are lanes (j, g, q=0))
                const int base = l & 16;
                const float actf = __shfl_sync(0xffffffffu, act, base + 4);
                const float actg = __shfl_sync(0xffffffffu, act, base + 8);
                const float acto = __shfl_sync(0xffffffffu, act, base + 12);

                if (lead) {
                    float c = fmaf(actf, c2[X], act * actg);
                    c2[X] = c;
                    const float e2c = __expf(2.f * c);
                    const float th  = 1.f - 2.f / (e2c + 1.f);
                    const float h   = acto * th;
                    const unsigned hval = __float_as_uint(h);
                    const unsigned hoff = (unsigned)((nxt * 2176) + (X * 1088));
                    const unsigned moff = (unsigned)(((X << 1) | (gs & 1)) << 3);
#pragma unroll
                    for (int p = 0; p < CL_SZ; p++)
                        asm volatile(
                            "st.async.shared::cluster.mbarrier::complete_tx::bytes.b32 "
                            "[%0], %1, [%2];"
                            :: "r"(rem_h0[p] + hoff), "r"(hval),
                               "r"(rem_mb0[p] + moff) : "memory");
                    g_houts[((size_t)t * BATCH + b0 + X) * (2 * HID)
                            + half + jglob] = h;
                }
            }
        }
    }
    // drain final exchanges (gs-1 == 8191) for both batches, then exit sync
    {
        const int e = 2 * T_STEPS - 1;
#pragma unroll
        for (int X = 0; X < 2; X++)
            mbar_wait_cl(mb0a + (unsigned)(((X << 1) | (e & 1)) << 3),
                         (unsigned)((e >> 1) & 1));
    }
    CLUSTER_SYNC();
}

// ---------------- launch ----------------------------------------------------
extern "C" void kernel_launch(void* const* d_in, const int* in_sizes, int n_in,
                              void* d_out, int out_size) {
    const float* carry_c = (const float*)d_in[0];
    const float* carry_h = (const float*)d_in[1];
    const float* x       = (const float*)d_in[2];
    const float* Wx_f    = (const float*)d_in[3];
    const float* Wh_f    = (const float*)d_in[4];
    const float* b_f     = (const float*)d_in[5];
    const float* Wx_b    = (const float*)d_in[6];
    const float* Wh_b    = (const float*)d_in[7];
    const float* b_b     = (const float*)d_in[8];
    const float* W_dense = (const float*)d_in[9];
    const float* b_dense = (const float*)d_in[10];
    float* out = (float*)d_out;

    float* xz_f; cudaGetSymbolAddress((void**)&xz_f, g_xz_f);
    float* xz_b; cudaGetSymbolAddress((void**)&xz_b, g_xz_b);

    dim3 g1(GATES / 128, (BATCH * T_STEPS) / 128);
    k_gemm_xz<<<g1, 256>>>(x, Wx_f, b_f, xz_f);
    k_gemm_xz<<<g1, 256>>>(x, Wx_b, b_b, xz_b);

    k_recur<<<NBLK, 512>>>(carry_c, carry_h, Wh_f, Wh_b);

    dim3 g2(OUTD / 128, (BATCH * T_STEPS) / 128);
    k_gemm_dense<<<g2, 256>>>(W_dense, b_dense, out);
}

// round 12
// speedup vs baseline: 1.2256x; 1.2256x over previous
#include <cuda_runtime.h>
#include <math.h>

#define T_STEPS 4096
#define BATCH   32
#define DIN     256
#define HID     256
#define GATES   1024
#define OUTD    512
#define CL_SZ   8
#define NBLK    128

__device__ float g_xz_f[(size_t)T_STEPS * BATCH * GATES];
__device__ float g_xz_b[(size_t)T_STEPS * BATCH * GATES];
__device__ float g_houts[(size_t)T_STEPS * BATCH * 2 * HID];

__device__ __forceinline__ float sigf(float x)  { return 1.0f / (1.0f + __expf(-x)); }
__device__ __forceinline__ float tanhf_(float x){ return 1.0f - 2.0f / (__expf(2.0f * x) + 1.0f); }

__device__ __forceinline__ unsigned long long ffma2(
    unsigned long long a, unsigned long long b, unsigned long long c) {
    unsigned long long d;
    asm("fma.rn.f32x2 %0, %1, %2, %3;" : "=l"(d) : "l"(a), "l"(b), "l"(c));
    return d;
}
__device__ __forceinline__ unsigned long long bcast2(float a) {
    unsigned long long d;
    asm("mov.b64 %0, {%1, %1};" : "=l"(d) : "f"(a));
    return d;
}
__device__ __forceinline__ unsigned smem_u32(const void* p) {
    return (unsigned)__cvta_generic_to_shared(p);
}
__device__ __forceinline__ void mbar_wait_cl(unsigned addr, unsigned parity) {
    asm volatile(
        "{\n\t.reg .pred P;\n"
        "LW%=:\n\t"
        "mbarrier.try_wait.parity.acquire.cluster.shared::cta.b64 P, [%0], %1, 0x989680;\n\t"
        "@P bra LD%=;\n\t"
        "bra LW%=;\n"
        "LD%=:\n\t}"
        :: "r"(addr), "r"(parity) : "memory");
}

#define CLUSTER_SYNC() do { \
    asm volatile("barrier.cluster.arrive.aligned;" ::: "memory"); \
    asm volatile("barrier.cluster.wait.aligned;"   ::: "memory"); \
} while (0)

// ---------------- GEMM 1: xz = x @ Wx + bias (unchanged, passing) -----------
__global__ void __launch_bounds__(256) k_gemm_xz(
    const float* __restrict__ A, const float* __restrict__ W,
    const float* __restrict__ bias, float* __restrict__ C)
{
    __shared__ float As[8][128];
    __shared__ float Bs[8][128];
    const int tid = threadIdx.x;
    const int n0 = blockIdx.x << 7, m0 = blockIdx.y << 7;
    const int am = tid >> 1, ak = (tid & 1) << 2;
    const int bk = tid >> 5, bn = (tid & 31) << 2;
    const int ty = tid >> 4, tx = tid & 15;
    unsigned long long acc2[8][4] = {};

    for (int k0 = 0; k0 < DIN; k0 += 8) {
        float4 av = *(const float4*)(A + (size_t)(m0 + am) * DIN + k0 + ak);
        float4 bv = *(const float4*)(W + (size_t)(k0 + bk) * GATES + n0 + bn);
        __syncthreads();
        As[ak + 0][am] = av.x; As[ak + 1][am] = av.y;
        As[ak + 2][am] = av.z; As[ak + 3][am] = av.w;
        *(float4*)&Bs[bk][bn] = bv;
        __syncthreads();
#pragma unroll
        for (int kk = 0; kk < 8; kk++) {
            float ar[8];
            *(float4*)&ar[0] = *(const float4*)&As[kk][(ty << 3) + 0];
            *(float4*)&ar[4] = *(const float4*)&As[kk][(ty << 3) + 4];
            union { float4 f; unsigned long long u[2]; } B0, B1;
            B0.f = *(const float4*)&Bs[kk][(tx << 3) + 0];
            B1.f = *(const float4*)&Bs[kk][(tx << 3) + 4];
#pragma unroll
            for (int r = 0; r < 8; r++) {
                unsigned long long a2 = bcast2(ar[r]);
                acc2[r][0] = ffma2(a2, B0.u[0], acc2[r][0]);
                acc2[r][1] = ffma2(a2, B0.u[1], acc2[r][1]);
                acc2[r][2] = ffma2(a2, B1.u[0], acc2[r][2]);
                acc2[r][3] = ffma2(a2, B1.u[1], acc2[r][3]);
            }
        }
    }
    float bi[8];
    *(float4*)&bi[0] = *(const float4*)(bias + n0 + (tx << 3) + 0);
    *(float4*)&bi[4] = *(const float4*)(bias + n0 + (tx << 3) + 4);
#pragma unroll
    for (int r = 0; r < 8; r++) {
        int m = m0 + (ty << 3) + r;
        int t = m & (T_STEPS - 1), b = m >> 12;
        float* dst = C + (size_t)(t * BATCH + b) * GATES + n0 + (tx << 3);
        union { unsigned long long u; float f[2]; } U;
        float o[8];
#pragma unroll
        for (int c4 = 0; c4 < 4; c4++) {
            U.u = acc2[r][c4];
            o[2 * c4 + 0] = U.f[0] + bi[2 * c4 + 0];
            o[2 * c4 + 1] = U.f[1] + bi[2 * c4 + 1];
        }
        *(float4*)(dst + 0) = *(float4*)&o[0];
        *(float4*)(dst + 4) = *(float4*)&o[4];
    }
}

// ---------------- GEMM 2: out = relu(h_cat) @ W_dense + b (unchanged) ------
__global__ void __launch_bounds__(256) k_gemm_dense(
    const float* __restrict__ W, const float* __restrict__ bias,
    float* __restrict__ out)
{
    __shared__ float As[8][128];
    __shared__ float Bs[8][128];
    const int tid = threadIdx.x;
    const int n0 = blockIdx.x << 7, m0 = blockIdx.y << 7;
    const int am = tid >> 1, ak = (tid & 1) << 2;
    const int bk = tid >> 5, bn = (tid & 31) << 2;
    const int ty = tid >> 4, tx = tid & 15;
    unsigned long long acc2[8][4] = {};

    for (int k0 = 0; k0 < 2 * HID; k0 += 8) {
        float4 av = *(const float4*)(g_houts + (size_t)(m0 + am) * (2 * HID) + k0 + ak);
        av.x = fmaxf(av.x, 0.f); av.y = fmaxf(av.y, 0.f);
        av.z = fmaxf(av.z, 0.f); av.w = fmaxf(av.w, 0.f);
        float4 bv = *(const float4*)(W + (size_t)(k0 + bk) * OUTD + n0 + bn);
        __syncthreads();
        As[ak + 0][am] = av.x; As[ak + 1][am] = av.y;
        As[ak + 2][am] = av.z; As[ak + 3][am] = av.w;
        *(float4*)&Bs[bk][bn] = bv;
        __syncthreads();
#pragma unroll
        for (int kk = 0; kk < 8; kk++) {
            float ar[8];
            *(float4*)&ar[0] = *(const float4*)&As[kk][(ty << 3) + 0];
            *(float4*)&ar[4] = *(const float4*)&As[kk][(ty << 3) + 4];
            union { float4 f; unsigned long long u[2]; } B0, B1;
            B0.f = *(const float4*)&Bs[kk][(tx << 3) + 0];
            B1.f = *(const float4*)&Bs[kk][(tx << 3) + 4];
#pragma unroll
            for (int r = 0; r < 8; r++) {
                unsigned long long a2 = bcast2(ar[r]);
                acc2[r][0] = ffma2(a2, B0.u[0], acc2[r][0]);
                acc2[r][1] = ffma2(a2, B0.u[1], acc2[r][1]);
                acc2[r][2] = ffma2(a2, B1.u[0], acc2[r][2]);
                acc2[r][3] = ffma2(a2, B1.u[1], acc2[r][3]);
            }
        }
    }
    float bi[8];
    *(float4*)&bi[0] = *(const float4*)(bias + n0 + (tx << 3) + 0);
    *(float4*)&bi[4] = *(const float4*)(bias + n0 + (tx << 3) + 4);
#pragma unroll
    for (int r = 0; r < 8; r++) {
        int m = m0 + (ty << 3) + r;
        int b = m & 31, t = m >> 5;
        float* dst = out + ((size_t)b * T_STEPS + t) * OUTD + n0 + (tx << 3);
        union { unsigned long long u; float f[2]; } U;
        float o[8];
#pragma unroll
        for (int c4 = 0; c4 < 4; c4++) {
            U.u = acc2[r][c4];
            o[2 * c4 + 0] = U.f[0] + bi[2 * c4 + 0];
            o[2 * c4 + 1] = U.f[1] + bi[2 * c4 + 1];
        }
        *(float4*)(dst + 0) = *(float4*)&o[0];
        *(float4*)(dst + 4) = *(float4*)&o[4];
    }
}

// ---------------- Recurrence: BULK DSMEM exchange (8 tx/step, not 512) -----
// R10 structure, but producers stage their 64 h values (256 B) locally and
// ONE thread issues 8 cp.async.bulk (s2s cluster, complete_tx at dest) —
// one 256-B copy per peer. h_s layout [buf][rank][batch][32] so each CTA's
// slice is contiguous in every peer. mbarrier gets 8 updates/step, not 512.
__global__ void __cluster_dims__(CL_SZ, 1, 1) __launch_bounds__(512, 1) k_recur(
    const float* __restrict__ carry_c, const float* __restrict__ carry_h,
    const float* __restrict__ Wh_f, const float* __restrict__ Wh_b)
{
    __shared__ __align__(16) float h_s[2][CL_SZ][2][32];  // [buf][rank][X][j] 4KB
    __shared__ __align__(16) float stage[2][2][32];       // [par][X][j] 512B
    __shared__ float p_s[4][2][128];
    __shared__ unsigned long long mb[2];

    const int tid   = threadIdx.x;
    const int rank  = blockIdx.x & (CL_SZ - 1);
    const int b0    = (blockIdx.x >> 3) << 1;
    const int jbase = rank << 5;

    const int q    = tid >> 7;                 // k-quarter 0..3
    const int col  = tid & 127;
    const int gate = col >> 5, jl = col & 31;
    const int gc   = (gate << 8) + jbase + jl;

    const bool isprod = (tid >= 448);          // warps 14-15
    const int  pt = tid - 448;
    const int  bp = pt >> 5, jp = pt & 31;
    const unsigned TXB = CL_SZ * 32u * 4u * 2u; // 2048 B per exchange

    // init h buffer 0: value (batch X, k) lives at h_s[0][k>>5][X][k&31]
    {
        const int X = tid >> 8, k = tid & 255;
        h_s[0][k >> 5][X][k & 31] = carry_h[(size_t)(b0 + X) * HID + k];
    }
    if (tid == 0) {
        asm volatile("mbarrier.init.shared.b64 [%0], %1;"
                     :: "r"(smem_u32(&mb[0])), "r"(1) : "memory");
        asm volatile("mbarrier.init.shared.b64 [%0], %1;"
                     :: "r"(smem_u32(&mb[1])), "r"(1) : "memory");
    }

    float c_reg = 0.f;
    if (isprod) c_reg = carry_c[(size_t)(b0 + bp) * HID + jbase + jp];

    // bulk-issue thread precomputes peer addresses of ITS slice + mbars
    unsigned rem_slice[CL_SZ];   // peer p's &h_s[0][rank][0][0]
    unsigned rem_mb[CL_SZ];      // peer p's &mb[0]
    if (tid == 448) {
        unsigned lh = smem_u32(&h_s[0][rank][0][0]);
        unsigned lm = smem_u32(&mb[0]);
#pragma unroll
        for (int p = 0; p < CL_SZ; p++) {
            asm("mapa.shared::cluster.u32 %0, %1, %2;"
                : "=r"(rem_slice[p]) : "r"(lh), "r"(p));
            asm("mapa.shared::cluster.u32 %0, %1, %2;"
                : "=r"(rem_mb[p]) : "r"(lm), "r"(p));
        }
    }
    __syncthreads();
    CLUSTER_SYNC();   // h bufs + mbars visible cluster-wide before step 0

    const unsigned mb0a = smem_u32(&mb[0]);
    const unsigned stage0 = smem_u32(&stage[0][0][0]);

    int gs = 0;
    for (int dir = 0; dir < 2; dir++) {
        const float* __restrict__ Wh = dir ? Wh_b : Wh_f;
        const float* __restrict__ xz = dir ? g_xz_b : g_xz_f;
        const int half = dir ? HID : 0;

        unsigned long long w2[32];
#pragma unroll
        for (int kk = 0; kk < 32; kk++) {
            union { float f[2]; unsigned long long u; } P;
            P.f[0] = Wh[(size_t)((q << 6) + 2 * kk + 0) * GATES + gc];
            P.f[1] = Wh[(size_t)((q << 6) + 2 * kk + 1) * GATES + gc];
            w2[kk] = P.u;
        }

        float xzp[4];
        if (isprod) {
            const int t0 = dir ? (T_STEPS - 1) : 0;
#pragma unroll
            for (int g = 0; g < 4; g++)
                xzp[g] = __ldcg(xz + ((size_t)t0 * BATCH + b0 + bp) * GATES
                                   + (g << 8) + jbase + jp);
        }

        for (int s = 0; s < T_STEPS; s++, gs++) {
            const int t   = dir ? (T_STEPS - 1 - s) : s;
            const int cur = gs & 1, nxt = cur ^ 1;

            if (gs > 0) {   // wait exchange gs-1 (all 2048 B landed)
                const int e = gs - 1;
                mbar_wait_cl(mb0a + (unsigned)((e & 1) << 3),
                             (unsigned)((e >> 1) & 1));
            }
            if (tid == 448)
                asm volatile(
                    "mbarrier.arrive.expect_tx.shared.b64 _, [%0], %1;"
                    :: "r"(mb0a + (unsigned)((gs & 1) << 3)), "r"(TXB)
                    : "memory");

            // partials over this thread's 64-k quarter (ranks 2q, 2q+1)
            unsigned long long a0 = 0ull, a1 = 0ull;
            {
                const float4* hA0 = (const float4*)&h_s[cur][2 * q + 0][0][0];
                const float4* hA1 = (const float4*)&h_s[cur][2 * q + 0][1][0];
                const float4* hB0 = (const float4*)&h_s[cur][2 * q + 1][0][0];
                const float4* hB1 = (const float4*)&h_s[cur][2 * q + 1][1][0];
#pragma unroll
                for (int i = 0; i < 8; i++) {
                    union { float4 f; unsigned long long u[2]; } U0, U1;
                    U0.f = hA0[i]; U1.f = hA1[i];
                    a0 = ffma2(U0.u[0], w2[2 * i + 0], a0);
                    a0 = ffma2(U0.u[1], w2[2 * i + 1], a0);
                    a1 = ffma2(U1.u[0], w2[2 * i + 0], a1);
                    a1 = ffma2(U1.u[1], w2[2 * i + 1], a1);
                }
#pragma unroll
                for (int i = 0; i < 8; i++) {
                    union { float4 f; unsigned long long u[2]; } U0, U1;
                    U0.f = hB0[i]; U1.f = hB1[i];
                    a0 = ffma2(U0.u[0], w2[16 + 2 * i + 0], a0);
                    a0 = ffma2(U0.u[1], w2[16 + 2 * i + 1], a0);
                    a1 = ffma2(U1.u[0], w2[16 + 2 * i + 0], a1);
                    a1 = ffma2(U1.u[1], w2[16 + 2 * i + 1], a1);
                }
            }
            {
                union { unsigned long long u; float f[2]; } A0, A1;
                A0.u = a0; A1.u = a1;
                p_s[q][0][col] = A0.f[0] + A0.f[1];
                p_s[q][1][col] = A1.f[0] + A1.f[1];
            }
            __syncthreads();

            if (isprod) {
                float z[4];
#pragma unroll
                for (int g = 0; g < 4; g++) {
                    const int cc = (g << 5) + jp;
                    z[g] = xzp[g] + p_s[0][bp][cc] + p_s[1][bp][cc]
                                  + p_s[2][bp][cc] + p_s[3][bp][cc];
                }
                c_reg = fmaf(sigf(z[1]), c_reg, sigf(z[0]) * tanhf_(z[2]));
                const float h = sigf(z[3]) * tanhf_(c_reg);
                stage[gs & 1][bp][jp] = h;
                g_houts[((size_t)t * BATCH + b0 + bp) * (2 * HID)
                        + half + jbase + jp] = h;
                if (s + 1 < T_STEPS) {
                    const int tn = dir ? (T_STEPS - 2 - s) : (s + 1);
#pragma unroll
                    for (int g = 0; g < 4; g++)
                        xzp[g] = __ldcg(xz + ((size_t)tn * BATCH + b0 + bp) * GATES
                                           + (g << 8) + jbase + jp);
                }
                // producer warps only: stage[] complete before bulk issue
                asm volatile("bar.sync 1, 64;" ::: "memory");
                if (tid == 448) {
                    asm volatile("fence.proxy.async.shared::cta;" ::: "memory");
                    const unsigned src  = stage0 + (unsigned)((gs & 1) << 8);
                    const unsigned doff = (unsigned)(nxt << 11);      // 2048 B
                    const unsigned moff = (unsigned)((gs & 1) << 3);
#pragma unroll
                    for (int p = 0; p < CL_SZ; p++)
                        asm volatile(
                            "cp.async.bulk.shared::cluster.shared::cta"
                            ".mbarrier::complete_tx::bytes "
                            "[%0], [%1], %2, [%3];"
                            :: "r"(rem_slice[p] + doff), "r"(src), "n"(256),
                               "r"(rem_mb[p] + moff) : "memory");
                }
            }
        }
    }
    // drain final exchange, then exit barrier (remote ops may target us)
    {
        const int e = 2 * T_STEPS - 1;
        mbar_wait_cl(mb0a + (unsigned)((e & 1) << 3), (unsigned)((e >> 1) & 1));
    }
    CLUSTER_SYNC();
}

// ---------------- launch ----------------------------------------------------
extern "C" void kernel_launch(void* const* d_in, const int* in_sizes, int n_in,
                              void* d_out, int out_size) {
    const float* carry_c = (const float*)d_in[0];
    const float* carry_h = (const float*)d_in[1];
    const float* x       = (const float*)d_in[2];
    const float* Wx_f    = (const float*)d_in[3];
    const float* Wh_f    = (const float*)d_in[4];
    const float* b_f     = (const float*)d_in[5];
    const float* Wx_b    = (const float*)d_in[6];
    const float* Wh_b    = (const float*)d_in[7];
    const float* b_b     = (const float*)d_in[8];
    const float* W_dense = (const float*)d_in[9];
    const float* b_dense = (const float*)d_in[10];
    float* out = (float*)d_out;

    float* xz_f; cudaGetSymbolAddress((void**)&xz_f, g_xz_f);
    float* xz_b; cudaGetSymbolAddress((void**)&xz_b, g_xz_b);

    dim3 g1(GATES / 128, (BATCH * T_STEPS) / 128);
    k_gemm_xz<<<g1, 256>>>(x, Wx_f, b_f, xz_f);
    k_gemm_xz<<<g1, 256>>>(x, Wx_b, b_b, xz_b);

    k_recur<<<NBLK, 512>>>(carry_c, carry_h, Wh_f, Wh_b);

    dim3 g2(OUTD / 128, (BATCH * T_STEPS) / 128);
    k_gemm_dense<<<g2, 256>>>(W_dense, b_dense, out);
}